// round 13
// baseline (speedup 1.0000x reference)
#include <cuda_runtime.h>
#include <cstdint>

// QuantileLoss: mean over [N,5] loss built from preds[N,5], target[N,3].
// R13: R12 geometry (128-thr blocks, 16KB tile, 12 blocks/SM) with TMA-bulk
//      staging: 2x cp.async.bulk per tile (preds 10240B + target 6144B)
//      replaces 1024 cp.async ops -> no LSU/L1tex per-op cost, completion
//      via mbarrier. Epilogue unchanged (zero kernel + one atomicAdd/block).

__global__ void zero_out_kernel(float* out) {
    if (threadIdx.x == 0) out[0] = 0.0f;
}

__device__ __forceinline__ float row_loss(
    float p0, float p1, float p2, float p3, float p4,
    float t0, float t1, float t2)
{
    float d0 = p0 - t0;
    float d1 = p1 - t1;
    float d2 = p2 - t2;
    float main_mse = d0 * d0 + d1 * d1 + d2 * d2;

    float pen = (p4 - t2) * 4.0f;

    float lo_th = t2 * 0.95f;
    float lo_d  = p3 - lo_th;
    float lower = (p3 > p2) ? pen : ((p3 > lo_th) ? 0.0f : lo_d * lo_d);

    float up_th = t2 * 1.05f;
    float up_d  = p4 - up_th;
    float upper = (p4 < p2) ? pen : ((p4 < up_th) ? 0.0f : up_d * up_d);

    return main_mse + lower + upper;
}

__device__ __forceinline__ float quad_rows(
    float4 p0, float4 p1, float4 p2, float4 p3, float4 p4,
    float4 g0, float4 g1, float4 g2)
{
    float s;
    s  = row_loss(p0.x, p0.y, p0.z, p0.w, p1.x, g0.x, g0.y, g0.z);
    s += row_loss(p1.y, p1.z, p1.w, p2.x, p2.y, g0.w, g1.x, g1.y);
    s += row_loss(p2.z, p2.w, p3.x, p3.y, p3.z, g1.z, g1.w, g2.x);
    s += row_loss(p3.w, p4.x, p4.y, p4.z, p4.w, g2.y, g2.z, g2.w);
    return s;
}

// Tile: 128 quads (= 512 rows) per block of 128 threads.
// smem: 640 float4 preds + 384 float4 target = 16 KB + mbarrier.
__global__ void __launch_bounds__(128)
quantile_loss_kernel(const float4* __restrict__ preds4,
                     const float4* __restrict__ tgt4,
                     const float*  __restrict__ preds,
                     const float*  __restrict__ target,
                     float* __restrict__ out,
                     int nquads, int n_rows, float inv_count)
{
    __shared__ __align__(16) float4 sh[1024];  // [0..639] preds, [640..1023] target
    __shared__ __align__(8) unsigned long long mbar;

    const int tid = threadIdx.x;
    const int qb  = blockIdx.x << 7;   // 128 quads per block
    float s = 0.0f;

    if (qb + 128 <= nquads) {
        // ---- fast path: TMA bulk staging (2 copies, 16384 bytes total) ----
        uint32_t sbase = (uint32_t)__cvta_generic_to_shared(sh);
        uint32_t mb    = (uint32_t)__cvta_generic_to_shared(&mbar);

        if (tid == 0) {
            asm volatile("mbarrier.init.shared.b64 [%0], 1;" :: "r"(mb) : "memory");
        }
        __syncthreads();   // mbar initialized before anyone waits / TMA lands

        if (tid == 0) {
            const void* pg = (const void*)(preds4 + (size_t)qb * 5);
            const void* tg = (const void*)(tgt4   + (size_t)qb * 3);
            asm volatile(
                "mbarrier.arrive.expect_tx.shared.b64 _, [%0], %1;"
                :: "r"(mb), "r"(16384u) : "memory");
            asm volatile(
                "cp.async.bulk.shared::cta.global.mbarrier::complete_tx::bytes "
                "[%0], [%1], %2, [%3];"
                :: "r"(sbase), "l"(pg), "r"(10240u), "r"(mb) : "memory");
            asm volatile(
                "cp.async.bulk.shared::cta.global.mbarrier::complete_tx::bytes "
                "[%0], [%1], %2, [%3];"
                :: "r"(sbase + 640u * 16u), "l"(tg), "r"(6144u), "r"(mb) : "memory");
        }

        // all threads wait for tile completion (phase 0)
        {
            uint32_t done;
            asm volatile(
                "{\n\t.reg .pred p;\n\t"
                "mbarrier.try_wait.parity.acquire.cta.shared::cta.b64 p, [%1], 0;\n\t"
                "selp.b32 %0, 1, 0, p;\n\t}"
                : "=r"(done) : "r"(mb) : "memory");
            while (!done) {
                asm volatile(
                    "{\n\t.reg .pred p;\n\t"
                    "mbarrier.try_wait.parity.acquire.cta.shared::cta.b64 p, [%1], 0, 0x989680;\n\t"
                    "selp.b32 %0, 1, 0, p;\n\t}"
                    : "=r"(done) : "r"(mb) : "memory");
            }
        }

        // strided smem reads: 80B / 48B lane strides are conflict-free
        float4 p0 = sh[tid * 5 + 0];
        float4 p1 = sh[tid * 5 + 1];
        float4 p2 = sh[tid * 5 + 2];
        float4 p3 = sh[tid * 5 + 3];
        float4 p4 = sh[tid * 5 + 4];
        float4 g0 = sh[640 + tid * 3 + 0];
        float4 g1 = sh[640 + tid * 3 + 1];
        float4 g2 = sh[640 + tid * 3 + 2];

        s = quad_rows(p0, p1, p2, p3, p4, g0, g1, g2);
    } else {
        // ---- partial tile: direct guarded loads (rare) ----
        int q = qb + tid;
        if (q < nquads) {
            float4 p0 = preds4[q * 5 + 0];
            float4 p1 = preds4[q * 5 + 1];
            float4 p2 = preds4[q * 5 + 2];
            float4 p3 = preds4[q * 5 + 3];
            float4 p4 = preds4[q * 5 + 4];
            float4 g0 = tgt4[q * 3 + 0];
            float4 g1 = tgt4[q * 3 + 1];
            float4 g2 = tgt4[q * 3 + 2];
            s = quad_rows(p0, p1, p2, p3, p4, g0, g1, g2);
        }
    }

    // tail rows (n_rows % 4) handled by one thread
    if (blockIdx.x == 0 && threadIdx.x == 0) {
        for (int r = nquads * 4; r < n_rows; r++) {
            s += row_loss(preds[r * 5 + 0], preds[r * 5 + 1], preds[r * 5 + 2],
                          preds[r * 5 + 3], preds[r * 5 + 4],
                          target[r * 3 + 0], target[r * 3 + 1], target[r * 3 + 2]);
        }
    }

    // intra-block reduce: warp shuffle -> smem (reuse tile) -> warp 0
    #pragma unroll
    for (int off = 16; off > 0; off >>= 1)
        s += __shfl_down_sync(0xFFFFFFFFu, s, off);

    __syncthreads();                      // all smem tile reads done
    float* ws = (float*)sh;               // reuse tile as warp-sum scratch
    int lane = tid & 31;
    int wid  = tid >> 5;
    if (lane == 0) ws[wid] = s;
    __syncthreads();

    if (wid == 0) {
        s = (lane < 4) ? ws[lane] : 0.0f;
        #pragma unroll
        for (int off = 2; off > 0; off >>= 1)
            s += __shfl_down_sync(0xFFFFFFFFu, s, off);
        if (lane == 0)
            atomicAdd(out, s * inv_count);
    }
}

extern "C" void kernel_launch(void* const* d_in, const int* in_sizes, int n_in,
                              void* d_out, int out_size)
{
    const float* preds  = (const float*)d_in[0];
    const float* target = (const float*)d_in[1];
    float* out = (float*)d_out;

    int n_rows = in_sizes[0] / 5;
    int nquads = n_rows / 4;
    float inv_count = 1.0f / (5.0f * (float)n_rows);

    zero_out_kernel<<<1, 32>>>(out);

    const int threads = 128;
    int blocks = (nquads + 127) / 128;
    if (blocks < 1) blocks = 1;

    quantile_loss_kernel<<<blocks, threads>>>(
        (const float4*)preds, (const float4*)target,
        preds, target, out, nquads, n_rows, inv_count);
}